// round 5
// baseline (speedup 1.0000x reference)
#include <cuda_runtime.h>
#include <cuda_bf16.h>
#include <cstdint>
#include <math.h>
#include <float.h>

// ---------------- problem constants ----------------
#define BB    8
#define NN    2048
#define DD    512
#define LL    6
#define HH    8
#define DHD   64
#define WSZ   128
#define NWIN  16
#define FFD   1365
#define FF2   2730          // 2*FFD
#define FFP   1376          // FFD padded (/16)
#define FF2P  2816          // 2*FFD padded (/128)
#define TT    (BB*NN)       // 16384 tokens
#define INNER 512

#define ATTN_SMEM (2*2*WSZ*DHD*4 + 2*WSZ*4)   // 132096 B

// ---------------- scratch (static device globals) ----------------
__device__ __align__(16) float g_h   [TT*DD];
__device__ __align__(16) float g_z   [TT*DD];
__device__ __align__(16) float g_qkv [TT*3*INNER];
__device__ __align__(16) float g_o   [TT*INNER];
__device__ __align__(16) float g_u   [(size_t)TT*FF2P];
__device__ __align__(16) float g_t   [(size_t)TT*FFP];
__device__ __align__(16) float g_pos [NN*DD];
__device__ __align__(16) float g_biasT[HH*2*WSZ*WSZ];   // [h][j][i]
__device__ __align__(16) float g_tab [2*WSZ*HH];
// tf32-rounded weights
__device__ __align__(16) float g_wqkvr[(size_t)LL*DD*3*INNER];
__device__ __align__(16) float g_woutr[(size_t)LL*INNER*DD];
__device__ __align__(16) float g_wff1p[(size_t)LL*DD*FF2P];
__device__ __align__(16) float g_wff2p[(size_t)LL*FFP*DD];
__device__ __align__(16) float g_wlogr[DD*DD];

// ---------------- tf32 helpers ----------------
__device__ __forceinline__ float roundtf(float f) {
    uint32_t o;
    asm("cvt.rna.tf32.f32 %0, %1;" : "=r"(o) : "f"(f));
    return __uint_as_float(o);
}
__device__ __forceinline__ void mma_tf32(float* c, const uint32_t* a, uint32_t b0, uint32_t b1) {
    asm volatile(
        "mma.sync.aligned.m16n8k8.row.col.f32.tf32.tf32.f32 "
        "{%0,%1,%2,%3},{%4,%5,%6,%7},{%8,%9},{%0,%1,%2,%3};"
        : "+f"(c[0]), "+f"(c[1]), "+f"(c[2]), "+f"(c[3])
        : "r"(a[0]), "r"(a[1]), "r"(a[2]), "r"(a[3]), "r"(b0), "r"(b1));
}
__device__ __forceinline__ void cp16(uint32_t s, const void* g) {
    asm volatile("cp.async.cg.shared.global [%0], [%1], 16;" :: "r"(s), "l"(g));
}

// ---------------- TGEMM (cp.async 4-stage): C = (addC?C:0) + A@B, inputs pre-rounded tf32 -----
// M%128==0, N%128==0, K%16==0. 128x128 tile, BK=16, 256 threads, 8 warps (2Mx4N of 64x32).
#define STAGES  4
#define APITCH  20
#define BPITCH  136
#define ASTRIDE (128*APITCH)    // floats per A stage
#define BSTRIDE (16*BPITCH)     // floats per B stage
#define GEMM_SMEM ((STAGES*(ASTRIDE+BSTRIDE))*4)

__global__ __launch_bounds__(256) void tgemm_kernel(
    const float* __restrict__ A, const float* __restrict__ B,
    float* __restrict__ C, int M, int N, int K, int addC)
{
    extern __shared__ uint32_t smbuf[];
    uint32_t* As = smbuf;
    uint32_t* Bs = smbuf + STAGES*ASTRIDE;

    int tid = threadIdx.x, lane = tid & 31, warp = tid >> 5;
    int wm = warp & 1, wn = warp >> 1;
    int bm = blockIdx.y << 7, bn = blockIdx.x << 7;
    int gid = lane >> 2, tig = lane & 3;

    int ar = tid >> 2, ac = (tid & 3) << 2;   // A: 128x16, 2x16B/thread (rows +0,+64)
    int br = tid >> 5, bc = (tid & 31) << 2;  // B: 16x128, 2x16B/thread (rows +0,+8)

    const float* Ag0 = A + (size_t)(bm + ar) * K + ac;
    const float* Ag1 = A + (size_t)(bm + ar + 64) * K + ac;
    const float* Bg0 = B + (size_t)br * N + bn + bc;
    const float* Bg1 = B + (size_t)(br + 8) * N + bn + bc;

    uint32_t sA0 = (uint32_t)__cvta_generic_to_shared(&As[ar * APITCH + ac]);
    uint32_t sA1 = (uint32_t)__cvta_generic_to_shared(&As[(ar + 64) * APITCH + ac]);
    uint32_t sB0 = (uint32_t)__cvta_generic_to_shared(&Bs[br * BPITCH + bc]);
    uint32_t sB1 = (uint32_t)__cvta_generic_to_shared(&Bs[(br + 8) * BPITCH + bc]);

    float acc[4][4][4];
    #pragma unroll
    for (int i = 0; i < 4; i++) {
        #pragma unroll
        for (int j = 0; j < 4; j++) {
            #pragma unroll
            for (int k = 0; k < 4; k++) acc[i][j][k] = 0.f;
        }
    }

    int tiles = K >> 4;

    // prologue: prefetch STAGES-1 tiles
    #pragma unroll
    for (int s = 0; s < STAGES - 1; s++) {
        if (s < tiles) {
            cp16(sA0 + s*ASTRIDE*4, Ag0 + s*16);
            cp16(sA1 + s*ASTRIDE*4, Ag1 + s*16);
            cp16(sB0 + s*BSTRIDE*4, Bg0 + (size_t)s*16*N);
            cp16(sB1 + s*BSTRIDE*4, Bg1 + (size_t)s*16*N);
        }
        asm volatile("cp.async.commit_group;");
    }

    for (int t = 0; t < tiles; t++) {
        asm volatile("cp.async.wait_group %0;" :: "n"(STAGES - 2));
        __syncthreads();

        int nt = t + STAGES - 1;
        if (nt < tiles) {
            int st = nt & (STAGES - 1);
            cp16(sA0 + st*ASTRIDE*4, Ag0 + nt*16);
            cp16(sA1 + st*ASTRIDE*4, Ag1 + nt*16);
            cp16(sB0 + st*BSTRIDE*4, Bg0 + (size_t)nt*16*N);
            cp16(sB1 + st*BSTRIDE*4, Bg1 + (size_t)nt*16*N);
        }
        asm volatile("cp.async.commit_group;");

        const uint32_t* Ab = As + (t & (STAGES - 1)) * ASTRIDE;
        const uint32_t* Bb = Bs + (t & (STAGES - 1)) * BSTRIDE;

        #pragma unroll
        for (int kk = 0; kk < 2; kk++) {
            uint32_t af[4][4];
            #pragma unroll
            for (int i = 0; i < 4; i++) {
                int r = wm*64 + i*16 + gid;
                int c = kk*8 + tig;
                af[i][0] = Ab[r * APITCH + c];
                af[i][1] = Ab[(r + 8) * APITCH + c];
                af[i][2] = Ab[r * APITCH + c + 4];
                af[i][3] = Ab[(r + 8) * APITCH + c + 4];
            }
            uint32_t bf[4][2];
            #pragma unroll
            for (int j = 0; j < 4; j++) {
                int c = wn*32 + j*8 + gid;
                int r = kk*8 + tig;
                bf[j][0] = Bb[r * BPITCH + c];
                bf[j][1] = Bb[(r + 4) * BPITCH + c];
            }
            #pragma unroll
            for (int i = 0; i < 4; i++) {
                #pragma unroll
                for (int j = 0; j < 4; j++) {
                    mma_tf32(acc[i][j], af[i], bf[j][0], bf[j][1]);
                }
            }
        }
    }

    #pragma unroll
    for (int i = 0; i < 4; i++) {
        int r0 = bm + wm*64 + i*16 + gid;
        #pragma unroll
        for (int j = 0; j < 4; j++) {
            int c0 = bn + wn*32 + j*8 + (tig << 1);
            float2* p0 = (float2*)&C[(size_t)r0 * N + c0];
            float2* p1 = (float2*)&C[(size_t)(r0 + 8) * N + c0];
            if (addC) {
                float2 v0 = *p0, v1 = *p1;
                v0.x += acc[i][j][0]; v0.y += acc[i][j][1];
                v1.x += acc[i][j][2]; v1.y += acc[i][j][3];
                *p0 = v0; *p1 = v1;
            } else {
                *p0 = make_float2(acc[i][j][0], acc[i][j][1]);
                *p1 = make_float2(acc[i][j][2], acc[i][j][3]);
            }
        }
    }
}

// ---------------- weight pad-copy + tf32 round ----------------
__global__ __launch_bounds__(256) void padw_kernel(
    const float* __restrict__ src, float* __restrict__ dst,
    int Lc, int K, int N, int Kp, int Np)
{
    size_t idx = (size_t)blockIdx.x * 256 + threadIdx.x;
    size_t total = (size_t)Lc * Kp * Np;
    if (idx >= total) return;
    int l = (int)(idx / ((size_t)Kp * Np));
    int rem = (int)(idx - (size_t)l * Kp * Np);
    int r = rem / Np, c = rem - r * Np;
    dst[idx] = (r < K && c < N) ? roundtf(src[((size_t)l * K + r) * N + c]) : 0.f;
}

// ---------------- block reduce (128 threads) ----------------
__device__ __forceinline__ float block_sum_128(float v) {
    __shared__ float sh[4];
    int lane = threadIdx.x & 31, wid = threadIdx.x >> 5;
    #pragma unroll
    for (int o = 16; o > 0; o >>= 1) v += __shfl_xor_sync(0xffffffffu, v, o);
    __syncthreads();
    if (lane == 0) sh[wid] = v;
    __syncthreads();
    return sh[0] + sh[1] + sh[2] + sh[3];
}

// ---------------- LayerNorm (f32 -> tf32-rounded f32) ----------------
__global__ __launch_bounds__(128) void ln_kernel(
    const float* __restrict__ in, const float* __restrict__ g,
    const float* __restrict__ b,  float* __restrict__ out)
{
    int tok = blockIdx.x;
    const float* row = in + (size_t)tok * DD;
    int tid = threadIdx.x;
    float v[4];
    float s = 0.f;
    #pragma unroll
    for (int k = 0; k < 4; k++) { v[k] = row[tid + k*128]; s += v[k]; }
    s = block_sum_128(s);
    float mean = s * (1.f / 512.f);
    float q = 0.f;
    #pragma unroll
    for (int k = 0; k < 4; k++) { float d = v[k] - mean; q += d * d; }
    q = block_sum_128(q);
    float rstd = rsqrtf(q * (1.f / 512.f) + 1e-5f);
    float* orow = out + (size_t)tok * DD;
    #pragma unroll
    for (int k = 0; k < 4; k++) {
        int d = tid + k*128;
        orow[d] = roundtf((v[k] - mean) * rstd * g[d] + b[d]);
    }
}

// ---------------- positional embedding ----------------
__global__ __launch_bounds__(128) void pos_kernel(float* __restrict__ pos)
{
    int n = blockIdx.x;
    for (int d = threadIdx.x; d < DD; d += 128) {
        int i = (d < 256) ? d : d - 256;
        float inv = (float)(1.0 / pow(10000.0, (double)(2 * i) / 512.0));
        float arg = (float)n * inv;
        double sv = (d < 256) ? sin((double)arg) : cos((double)arg);
        pos[n * DD + d] = (float)sv;
    }
}

// ---------------- embedding + pos add ----------------
__global__ __launch_bounds__(128) void embed_kernel(
    const int* __restrict__ x, const float* __restrict__ emb,
    const float* __restrict__ pos, float* __restrict__ h)
{
    int tok = blockIdx.x;
    int n = tok & (NN - 1);
    int xv = x[tok];
    float mk = (xv != 0) ? 1.f : 0.f;
    const float* erow = emb + (size_t)xv * DD;
    const float* prow = pos + (size_t)n * DD;
    float* hrow = h + (size_t)tok * DD;
    for (int d = threadIdx.x; d < DD; d += 128)
        hrow[d] = erow[d] * mk + prow[d];
}

// ---------------- dynamic position bias MLP ----------------
__global__ __launch_bounds__(256) void dpb_tab_kernel(
    const float* __restrict__ w1, const float* __restrict__ b1,
    const float* __restrict__ w2, const float* __restrict__ b2,
    const float* __restrict__ w3, const float* __restrict__ b3,
    float* __restrict__ tab)
{
    int r = blockIdx.x;
    int c = threadIdx.x;
    __shared__ float h1[256];
    __shared__ float h2[256];
    float v = (float)r * w1[c] + b1[c];
    h1[c] = v / (1.f + expf(-v));
    __syncthreads();
    float s = b2[c];
    #pragma unroll 4
    for (int k = 0; k < 256; k++) s += h1[k] * w2[k * 256 + c];
    h2[c] = s / (1.f + expf(-s));
    __syncthreads();
    if (c < HH) {
        float t = b3[c];
        #pragma unroll 4
        for (int k = 0; k < 256; k++) t += h2[k] * w3[k * HH + c];
        tab[r * HH + c] = t;
    }
}

// ---------------- bias fill, transposed: biasT[h][j][i] = tab[|i+128-j|][h] ----------------
__global__ __launch_bounds__(256) void dpb_bias_kernel(
    const float* __restrict__ tab, float* __restrict__ biasT)
{
    int idx = blockIdx.x * 256 + threadIdx.x;
    int hh = idx >> 15;
    int j  = (idx >> 7) & 255;
    int i  = idx & 127;
    int a  = abs(i + 128 - j);
    biasT[idx] = tab[a * HH + hh];
}

// ---------------- windowed attention (online softmax, contiguous j-range) ----------------
__global__ __launch_bounds__(128) void attn_kernel(
    const float* __restrict__ qkv, const int* __restrict__ x,
    const float* __restrict__ biasT, float* __restrict__ o)
{
    extern __shared__ float sm[];
    float* ks = sm;                 // [256][64]
    float* vs = sm + 2*WSZ*DHD;     // [256][64]
    int*   km = (int*)(sm + 4*WSZ*DHD);
    int w = blockIdx.x, h = blockIdx.y, b = blockIdx.z;
    int tid = threadIdx.x;

    for (int e = tid; e < 2*WSZ; e += 128) {
        int ok;
        if (e < WSZ) ok = (w > 0) ? (x[b * NN + (w - 1) * WSZ + e] != 0) : 0;
        else         ok = (x[b * NN + w * WSZ + (e - WSZ)] != 0);
        km[e] = ok;
    }
    for (int e = tid; e < 2*WSZ*DHD; e += 128) {
        int j = e >> 6, d = e & 63;
        float kv, vv;
        if (j < WSZ && w == 0) { kv = -1.f; vv = -1.f; }
        else {
            int tok = (j < WSZ) ? (b * NN + (w - 1) * WSZ + j)
                                : (b * NN + w * WSZ + (j - WSZ));
            size_t base = (size_t)tok * (3*INNER) + h * DHD + d;
            kv = qkv[base + INNER];
            vv = qkv[base + 2*INNER];
        }
        ks[e] = kv; vs[e] = vv;
    }
    __syncthreads();

    int i = tid;
    float q[DHD];
    {
        size_t qb = (size_t)(b * NN + w * WSZ + i) * (3*INNER) + h * DHD;
        #pragma unroll
        for (int d = 0; d < DHD; d++) q[d] = qkv[qb + d] * 0.125f;
    }
    const float* brow = biasT + (size_t)h * 2*WSZ*WSZ + i;

    float m = -FLT_MAX, l = 0.f;
    float acc[DHD];
    #pragma unroll
    for (int d = 0; d < DHD; d++) acc[d] = 0.f;

    // valid keys are exactly j in [i, i+WSZ] (129 candidates)
    for (int j = i; j <= i + WSZ; j++) {
        bool valid = (km[j] != 0) && (j >= WSZ || w > 0);
        if (valid) {
            const float* kr = ks + j * DHD;
            float s0 = 0.f, s1 = 0.f, s2 = 0.f, s3 = 0.f;
            #pragma unroll
            for (int d = 0; d < DHD; d += 4) {
                s0 += q[d]   * kr[d];
                s1 += q[d+1] * kr[d+1];
                s2 += q[d+2] * kr[d+2];
                s3 += q[d+3] * kr[d+3];
            }
            float s = (s0 + s1) + (s2 + s3) + brow[(size_t)j * WSZ];
            if (s > m) {
                float cc = (m == -FLT_MAX) ? 0.f : expf(m - s);
                l *= cc;
                #pragma unroll
                for (int d = 0; d < DHD; d++) acc[d] *= cc;
                m = s;
            }
            float p = expf(s - m);
            l += p;
            const float* vr = vs + j * DHD;
            #pragma unroll
            for (int d = 0; d < DHD; d++) acc[d] += p * vr[d];
        }
    }

    if (m == -FLT_MAX) {
        // all-masked row: softmax over all-equal logits -> uniform over all 256 (incl. -1.0 pads)
        #pragma unroll
        for (int d = 0; d < DHD; d++) acc[d] = 0.f;
        for (int j = 0; j < 2*WSZ; j++) {
            const float* vr = vs + j * DHD;
            #pragma unroll
            for (int d = 0; d < DHD; d++) acc[d] += vr[d];
        }
        l = 256.f;
    }
    float inv = 1.f / l;
    size_t obase = (size_t)(b * NN + w * WSZ + i) * INNER + h * DHD;
    #pragma unroll
    for (int d = 0; d < DHD; d++) o[obase + d] = roundtf(acc[d] * inv);
}

// ---------------- GEGLU -> tf32-rounded, zero pad to FFP ----------------
__global__ __launch_bounds__(256) void geglu_kernel(
    const float* __restrict__ u, float* __restrict__ t)
{
    int mrow = blockIdx.x;
    const float* ur = u + (size_t)mrow * FF2P;
    float* tr = t + (size_t)mrow * FFP;
    for (int f = threadIdx.x; f < FFP; f += 256) {
        float r = 0.f;
        if (f < FFD) {
            float a = ur[f], g = ur[FFD + f];
            float ge = 0.5f * g * (1.f + erff(g * 0.70710678118654752f));
            r = roundtf(a * ge);
        }
        tr[f] = r;
    }
}

// ---------------- launch ----------------
extern "C" void kernel_launch(void* const* d_in, const int* in_sizes, int n_in,
                              void* d_out, int out_size)
{
    const int*   x        = (const int*)  d_in[0];
    const float* emb      = (const float*)d_in[1];
    const float* ln_ag    = (const float*)d_in[2];
    const float* ln_ab    = (const float*)d_in[3];
    const float* w_qkv    = (const float*)d_in[4];
    const float* w_out    = (const float*)d_in[5];
    const float* ln_fg    = (const float*)d_in[6];
    const float* ln_fb    = (const float*)d_in[7];
    const float* w_ff1    = (const float*)d_in[8];
    const float* w_ff2    = (const float*)d_in[9];
    const float* dpb_w1   = (const float*)d_in[10];
    const float* dpb_b1   = (const float*)d_in[11];
    const float* dpb_w2   = (const float*)d_in[12];
    const float* dpb_b2   = (const float*)d_in[13];
    const float* dpb_w3   = (const float*)d_in[14];
    const float* dpb_b3   = (const float*)d_in[15];
    const float* ln_og    = (const float*)d_in[16];
    const float* ln_ob    = (const float*)d_in[17];
    const float* w_logits = (const float*)d_in[18];
    float* out = (float*)d_out;

    float *h, *z, *qkv, *o, *u, *t, *pos, *biasT, *tab;
    float *wqkvr, *woutr, *wff1p, *wff2p, *wlogr;
    cudaGetSymbolAddress((void**)&h,     g_h);
    cudaGetSymbolAddress((void**)&z,     g_z);
    cudaGetSymbolAddress((void**)&qkv,   g_qkv);
    cudaGetSymbolAddress((void**)&o,     g_o);
    cudaGetSymbolAddress((void**)&u,     g_u);
    cudaGetSymbolAddress((void**)&t,     g_t);
    cudaGetSymbolAddress((void**)&pos,   g_pos);
    cudaGetSymbolAddress((void**)&biasT, g_biasT);
    cudaGetSymbolAddress((void**)&tab,   g_tab);
    cudaGetSymbolAddress((void**)&wqkvr, g_wqkvr);
    cudaGetSymbolAddress((void**)&woutr, g_woutr);
    cudaGetSymbolAddress((void**)&wff1p, g_wff1p);
    cudaGetSymbolAddress((void**)&wff2p, g_wff2p);
    cudaGetSymbolAddress((void**)&wlogr, g_wlogr);

    cudaFuncSetAttribute(attn_kernel, cudaFuncAttributeMaxDynamicSharedMemorySize, ATTN_SMEM);
    cudaFuncSetAttribute(tgemm_kernel, cudaFuncAttributeMaxDynamicSharedMemorySize, GEMM_SMEM);

    pos_kernel   <<<NN, 128>>>(pos);
    embed_kernel <<<TT, 128>>>(x, emb, pos, h);
    dpb_tab_kernel <<<2*WSZ, 256>>>(dpb_w1, dpb_b1, dpb_w2, dpb_b2, dpb_w3, dpb_b3, tab);
    dpb_bias_kernel<<<(HH*WSZ*2*WSZ)/256, 256>>>(tab, biasT);

    // weight prep: tf32 rounding (+ padding for FF dims)
    {
        size_t n;
        n = (size_t)LL * DD * 3*INNER;
        padw_kernel<<<(unsigned)((n + 255)/256), 256>>>(w_qkv, wqkvr, 1, LL*DD, 3*INNER, LL*DD, 3*INNER);
        n = (size_t)LL * INNER * DD;
        padw_kernel<<<(unsigned)((n + 255)/256), 256>>>(w_out, woutr, 1, LL*INNER, DD, LL*INNER, DD);
        n = (size_t)LL * DD * FF2P;
        padw_kernel<<<(unsigned)((n + 255)/256), 256>>>(w_ff1, wff1p, LL, DD, FF2, DD, FF2P);
        n = (size_t)LL * FFP * DD;
        padw_kernel<<<(unsigned)((n + 255)/256), 256>>>(w_ff2, wff2p, LL, FFD, DD, FFP, DD);
        n = (size_t)DD * DD;
        padw_kernel<<<(unsigned)((n + 255)/256), 256>>>(w_logits, wlogr, 1, DD, DD, DD, DD);
    }

    for (int l = 0; l < LL; l++) {
        ln_kernel<<<TT, 128>>>(h, ln_ag + (size_t)l*DD, ln_ab + (size_t)l*DD, z);
        tgemm_kernel<<<dim3(12, 128), 256, GEMM_SMEM>>>(z, wqkvr + (size_t)l*DD*3*INNER, qkv,
                                                        TT, 3*INNER, DD, 0);
        attn_kernel<<<dim3(NWIN, HH, BB), 128, ATTN_SMEM>>>(qkv, x, biasT, o);
        tgemm_kernel<<<dim3(4, 128), 256, GEMM_SMEM>>>(o, woutr + (size_t)l*INNER*DD, h,
                                                       TT, DD, INNER, 1);
        ln_kernel<<<TT, 128>>>(h, ln_fg + (size_t)l*DD, ln_fb + (size_t)l*DD, z);
        tgemm_kernel<<<dim3(FF2P/128, 128), 256, GEMM_SMEM>>>(z, wff1p + (size_t)l*DD*FF2P, u,
                                                              TT, FF2P, DD, 0);
        geglu_kernel<<<TT, 256>>>(u, t);
        tgemm_kernel<<<dim3(4, 128), 256, GEMM_SMEM>>>(t, wff2p + (size_t)l*FFP*DD, h,
                                                       TT, DD, FFP, 1);
    }
    ln_kernel<<<TT, 128>>>(h, ln_og, ln_ob, z);
    tgemm_kernel<<<dim3(4, 128), 256, GEMM_SMEM>>>(z, wlogr, out, TT, DD, DD, 0);
}

// round 6
// speedup vs baseline: 2.0022x; 2.0022x over previous
#include <cuda_runtime.h>
#include <cuda_bf16.h>
#include <cstdint>
#include <math.h>
#include <float.h>

// ---------------- problem constants ----------------
#define BB    8
#define NN    2048
#define DD    512
#define LL    6
#define HH    8
#define DHD   64
#define WSZ   128
#define NWIN  16
#define FFD   1365
#define FF2   2730          // 2*FFD
#define FFP   1376          // FFD padded (/16)
#define FF2P  2816          // 2*FFD padded (/128)
#define TT    (BB*NN)       // 16384 tokens
#define INNER 512

#define KPITCH 65           // smem row pitch for K/V (conflict-free diagonal reads)
#define ATTN_SMEM ((2*2*WSZ*KPITCH + 2*WSZ + 2*WSZ) * 4)   // ks+vs + km + biasd, ~135KB

// ---------------- scratch (static device globals) ----------------
__device__ __align__(16) float g_h   [TT*DD];
__device__ __align__(16) float g_z   [TT*DD];
__device__ __align__(16) float g_qkv [TT*3*INNER];
__device__ __align__(16) float g_o   [TT*INNER];
__device__ __align__(16) float g_u   [(size_t)TT*FF2P];
__device__ __align__(16) float g_t   [(size_t)TT*FFP];
__device__ __align__(16) float g_pos [NN*DD];
__device__ __align__(16) float g_tab [2*WSZ*HH];
// tf32-rounded weights
__device__ __align__(16) float g_wqkvr[(size_t)LL*DD*3*INNER];
__device__ __align__(16) float g_woutr[(size_t)LL*INNER*DD];
__device__ __align__(16) float g_wff1p[(size_t)LL*DD*FF2P];
__device__ __align__(16) float g_wff2p[(size_t)LL*FFP*DD];
__device__ __align__(16) float g_wlogr[DD*DD];

// ---------------- tf32 helpers ----------------
__device__ __forceinline__ float roundtf(float f) {
    uint32_t o;
    asm("cvt.rna.tf32.f32 %0, %1;" : "=r"(o) : "f"(f));
    return __uint_as_float(o);
}
__device__ __forceinline__ void mma_tf32(float* c, const uint32_t* a, uint32_t b0, uint32_t b1) {
    asm volatile(
        "mma.sync.aligned.m16n8k8.row.col.f32.tf32.tf32.f32 "
        "{%0,%1,%2,%3},{%4,%5,%6,%7},{%8,%9},{%0,%1,%2,%3};"
        : "+f"(c[0]), "+f"(c[1]), "+f"(c[2]), "+f"(c[3])
        : "r"(a[0]), "r"(a[1]), "r"(a[2]), "r"(a[3]), "r"(b0), "r"(b1));
}
__device__ __forceinline__ void cp16(uint32_t s, const void* g) {
    asm volatile("cp.async.cg.shared.global [%0], [%1], 16;" :: "r"(s), "l"(g));
}

// ---------------- TGEMM (cp.async 4-stage): C = (addC?C:0) + A@B, inputs pre-rounded tf32 -----
#define STAGES  4
#define APITCH  20
#define BPITCH  136
#define ASTRIDE (128*APITCH)
#define BSTRIDE (16*BPITCH)
#define GEMM_SMEM ((STAGES*(ASTRIDE+BSTRIDE))*4)

__global__ __launch_bounds__(256) void tgemm_kernel(
    const float* __restrict__ A, const float* __restrict__ B,
    float* __restrict__ C, int M, int N, int K, int addC)
{
    extern __shared__ uint32_t smbuf[];
    uint32_t* As = smbuf;
    uint32_t* Bs = smbuf + STAGES*ASTRIDE;

    int tid = threadIdx.x, lane = tid & 31, warp = tid >> 5;
    int wm = warp & 1, wn = warp >> 1;
    int bm = blockIdx.y << 7, bn = blockIdx.x << 7;
    int gid = lane >> 2, tig = lane & 3;

    int ar = tid >> 2, ac = (tid & 3) << 2;
    int br = tid >> 5, bc = (tid & 31) << 2;

    const float* Ag0 = A + (size_t)(bm + ar) * K + ac;
    const float* Ag1 = A + (size_t)(bm + ar + 64) * K + ac;
    const float* Bg0 = B + (size_t)br * N + bn + bc;
    const float* Bg1 = B + (size_t)(br + 8) * N + bn + bc;

    uint32_t sA0 = (uint32_t)__cvta_generic_to_shared(&As[ar * APITCH + ac]);
    uint32_t sA1 = (uint32_t)__cvta_generic_to_shared(&As[(ar + 64) * APITCH + ac]);
    uint32_t sB0 = (uint32_t)__cvta_generic_to_shared(&Bs[br * BPITCH + bc]);
    uint32_t sB1 = (uint32_t)__cvta_generic_to_shared(&Bs[(br + 8) * BPITCH + bc]);

    float acc[4][4][4];
    #pragma unroll
    for (int i = 0; i < 4; i++) {
        #pragma unroll
        for (int j = 0; j < 4; j++) {
            #pragma unroll
            for (int k = 0; k < 4; k++) acc[i][j][k] = 0.f;
        }
    }

    int tiles = K >> 4;

    #pragma unroll
    for (int s = 0; s < STAGES - 1; s++) {
        if (s < tiles) {
            cp16(sA0 + s*ASTRIDE*4, Ag0 + s*16);
            cp16(sA1 + s*ASTRIDE*4, Ag1 + s*16);
            cp16(sB0 + s*BSTRIDE*4, Bg0 + (size_t)s*16*N);
            cp16(sB1 + s*BSTRIDE*4, Bg1 + (size_t)s*16*N);
        }
        asm volatile("cp.async.commit_group;");
    }

    for (int t = 0; t < tiles; t++) {
        asm volatile("cp.async.wait_group %0;" :: "n"(STAGES - 2));
        __syncthreads();

        int nt = t + STAGES - 1;
        if (nt < tiles) {
            int st = nt & (STAGES - 1);
            cp16(sA0 + st*ASTRIDE*4, Ag0 + nt*16);
            cp16(sA1 + st*ASTRIDE*4, Ag1 + nt*16);
            cp16(sB0 + st*BSTRIDE*4, Bg0 + (size_t)nt*16*N);
            cp16(sB1 + st*BSTRIDE*4, Bg1 + (size_t)nt*16*N);
        }
        asm volatile("cp.async.commit_group;");

        const uint32_t* Ab = As + (t & (STAGES - 1)) * ASTRIDE;
        const uint32_t* Bb = Bs + (t & (STAGES - 1)) * BSTRIDE;

        #pragma unroll
        for (int kk = 0; kk < 2; kk++) {
            uint32_t af[4][4];
            #pragma unroll
            for (int i = 0; i < 4; i++) {
                int r = wm*64 + i*16 + gid;
                int c = kk*8 + tig;
                af[i][0] = Ab[r * APITCH + c];
                af[i][1] = Ab[(r + 8) * APITCH + c];
                af[i][2] = Ab[r * APITCH + c + 4];
                af[i][3] = Ab[(r + 8) * APITCH + c + 4];
            }
            uint32_t bf[4][2];
            #pragma unroll
            for (int j = 0; j < 4; j++) {
                int c = wn*32 + j*8 + gid;
                int r = kk*8 + tig;
                bf[j][0] = Bb[r * BPITCH + c];
                bf[j][1] = Bb[(r + 4) * BPITCH + c];
            }
            #pragma unroll
            for (int i = 0; i < 4; i++) {
                #pragma unroll
                for (int j = 0; j < 4; j++) {
                    mma_tf32(acc[i][j], af[i], bf[j][0], bf[j][1]);
                }
            }
        }
    }

    #pragma unroll
    for (int i = 0; i < 4; i++) {
        int r0 = bm + wm*64 + i*16 + gid;
        #pragma unroll
        for (int j = 0; j < 4; j++) {
            int c0 = bn + wn*32 + j*8 + (tig << 1);
            float2* p0 = (float2*)&C[(size_t)r0 * N + c0];
            float2* p1 = (float2*)&C[(size_t)(r0 + 8) * N + c0];
            if (addC) {
                float2 v0 = *p0, v1 = *p1;
                v0.x += acc[i][j][0]; v0.y += acc[i][j][1];
                v1.x += acc[i][j][2]; v1.y += acc[i][j][3];
                *p0 = v0; *p1 = v1;
            } else {
                *p0 = make_float2(acc[i][j][0], acc[i][j][1]);
                *p1 = make_float2(acc[i][j][2], acc[i][j][3]);
            }
        }
    }
}

// ---------------- weight pad-copy + tf32 round ----------------
__global__ __launch_bounds__(256) void padw_kernel(
    const float* __restrict__ src, float* __restrict__ dst,
    int Lc, int K, int N, int Kp, int Np)
{
    size_t idx = (size_t)blockIdx.x * 256 + threadIdx.x;
    size_t total = (size_t)Lc * Kp * Np;
    if (idx >= total) return;
    int l = (int)(idx / ((size_t)Kp * Np));
    int rem = (int)(idx - (size_t)l * Kp * Np);
    int r = rem / Np, c = rem - r * Np;
    dst[idx] = (r < K && c < N) ? roundtf(src[((size_t)l * K + r) * N + c]) : 0.f;
}

// ---------------- block reduce (128 threads) ----------------
__device__ __forceinline__ float block_sum_128(float v) {
    __shared__ float sh[4];
    int lane = threadIdx.x & 31, wid = threadIdx.x >> 5;
    #pragma unroll
    for (int o = 16; o > 0; o >>= 1) v += __shfl_xor_sync(0xffffffffu, v, o);
    __syncthreads();
    if (lane == 0) sh[wid] = v;
    __syncthreads();
    return sh[0] + sh[1] + sh[2] + sh[3];
}

// ---------------- LayerNorm (f32 -> tf32-rounded f32) ----------------
__global__ __launch_bounds__(128) void ln_kernel(
    const float* __restrict__ in, const float* __restrict__ g,
    const float* __restrict__ b,  float* __restrict__ out)
{
    int tok = blockIdx.x;
    const float* row = in + (size_t)tok * DD;
    int tid = threadIdx.x;
    float v[4];
    float s = 0.f;
    #pragma unroll
    for (int k = 0; k < 4; k++) { v[k] = row[tid + k*128]; s += v[k]; }
    s = block_sum_128(s);
    float mean = s * (1.f / 512.f);
    float q = 0.f;
    #pragma unroll
    for (int k = 0; k < 4; k++) { float d = v[k] - mean; q += d * d; }
    q = block_sum_128(q);
    float rstd = rsqrtf(q * (1.f / 512.f) + 1e-5f);
    float* orow = out + (size_t)tok * DD;
    #pragma unroll
    for (int k = 0; k < 4; k++) {
        int d = tid + k*128;
        orow[d] = roundtf((v[k] - mean) * rstd * g[d] + b[d]);
    }
}

// ---------------- positional embedding ----------------
__global__ __launch_bounds__(128) void pos_kernel(float* __restrict__ pos)
{
    int n = blockIdx.x;
    for (int d = threadIdx.x; d < DD; d += 128) {
        int i = (d < 256) ? d : d - 256;
        float inv = (float)(1.0 / pow(10000.0, (double)(2 * i) / 512.0));
        float arg = (float)n * inv;
        double sv = (d < 256) ? sin((double)arg) : cos((double)arg);
        pos[n * DD + d] = (float)sv;
    }
}

// ---------------- embedding + pos add ----------------
__global__ __launch_bounds__(128) void embed_kernel(
    const int* __restrict__ x, const float* __restrict__ emb,
    const float* __restrict__ pos, float* __restrict__ h)
{
    int tok = blockIdx.x;
    int n = tok & (NN - 1);
    int xv = x[tok];
    float mk = (xv != 0) ? 1.f : 0.f;
    const float* erow = emb + (size_t)xv * DD;
    const float* prow = pos + (size_t)n * DD;
    float* hrow = h + (size_t)tok * DD;
    for (int d = threadIdx.x; d < DD; d += 128)
        hrow[d] = erow[d] * mk + prow[d];
}

// ---------------- dynamic position bias MLP: tab[2W][H] ----------------
__global__ __launch_bounds__(256) void dpb_tab_kernel(
    const float* __restrict__ w1, const float* __restrict__ b1,
    const float* __restrict__ w2, const float* __restrict__ b2,
    const float* __restrict__ w3, const float* __restrict__ b3,
    float* __restrict__ tab)
{
    int r = blockIdx.x;
    int c = threadIdx.x;
    __shared__ float h1[256];
    __shared__ float h2[256];
    float v = (float)r * w1[c] + b1[c];
    h1[c] = v / (1.f + expf(-v));
    __syncthreads();
    float s = b2[c];
    #pragma unroll 4
    for (int k = 0; k < 256; k++) s += h1[k] * w2[k * 256 + c];
    h2[c] = s / (1.f + expf(-s));
    __syncthreads();
    if (c < HH) {
        float t = b3[c];
        #pragma unroll 4
        for (int k = 0; k < 256; k++) t += h2[k] * w3[k * HH + c];
        tab[r * HH + c] = t;
    }
}

// ---------------- windowed attention (online softmax, diagonal bias, conflict-free) ----------
// bias[h][i][j] = tab[|i+128-j|][h]; with j = i+off: |128-off| -> depends only on off.
__global__ __launch_bounds__(128) void attn_kernel(
    const float* __restrict__ qkv, const int* __restrict__ x,
    const float* __restrict__ tab, float* __restrict__ o)
{
    extern __shared__ float sm[];
    float* ks    = sm;                          // [256][KPITCH]
    float* vs    = sm + 2*WSZ*KPITCH;           // [256][KPITCH]
    int*   km    = (int*)(sm + 4*WSZ*KPITCH);   // [256]
    float* biasd = sm + 4*WSZ*KPITCH + 2*WSZ;   // [129]
    int w = blockIdx.x, h = blockIdx.y, b = blockIdx.z;
    int tid = threadIdx.x;

    for (int e = tid; e < 2*WSZ; e += 128) {
        int ok;
        if (e < WSZ) ok = (w > 0) ? (x[b * NN + (w - 1) * WSZ + e] != 0) : 0;
        else         ok = (x[b * NN + w * WSZ + (e - WSZ)] != 0);
        km[e] = ok;
        if (e <= WSZ) biasd[e] = tab[(WSZ - e) * HH + h];   // biasd[off] = tab[128-off][h]
    }
    for (int e = tid; e < 2*WSZ*DHD; e += 128) {
        int j = e >> 6, d = e & 63;
        float kv, vv;
        if (j < WSZ && w == 0) { kv = -1.f; vv = -1.f; }
        else {
            int tok = (j < WSZ) ? (b * NN + (w - 1) * WSZ + j)
                                : (b * NN + w * WSZ + (j - WSZ));
            size_t base = (size_t)tok * (3*INNER) + h * DHD + d;
            kv = qkv[base + INNER];
            vv = qkv[base + 2*INNER];
        }
        ks[j * KPITCH + d] = kv;
        vs[j * KPITCH + d] = vv;
    }
    __syncthreads();

    int i = tid;
    float q[DHD];
    {
        size_t qb = (size_t)(b * NN + w * WSZ + i) * (3*INNER) + h * DHD;
        #pragma unroll
        for (int d = 0; d < DHD; d++) q[d] = qkv[qb + d] * 0.125f;
    }

    float m = -FLT_MAX, l = 0.f;
    float acc[DHD];
    #pragma unroll
    for (int d = 0; d < DHD; d++) acc[d] = 0.f;

    // valid keys: j = i + off, off in [0,128]; km[j]==0 encodes both pad and w==0-prev-window
    for (int off = 0; off <= WSZ; off++) {
        int j = i + off;
        if (km[j] != 0) {
            const float* kr = ks + j * KPITCH;
            float s0 = 0.f, s1 = 0.f, s2 = 0.f, s3 = 0.f;
            #pragma unroll
            for (int d = 0; d < DHD; d += 4) {
                s0 += q[d]   * kr[d];
                s1 += q[d+1] * kr[d+1];
                s2 += q[d+2] * kr[d+2];
                s3 += q[d+3] * kr[d+3];
            }
            float s = (s0 + s1) + (s2 + s3) + biasd[off];
            if (s > m) {
                float cc = (m == -FLT_MAX) ? 0.f : expf(m - s);
                l *= cc;
                #pragma unroll
                for (int d = 0; d < DHD; d++) acc[d] *= cc;
                m = s;
            }
            float p = expf(s - m);
            l += p;
            const float* vr = vs + j * KPITCH;
            #pragma unroll
            for (int d = 0; d < DHD; d++) acc[d] += p * vr[d];
        }
    }

    if (m == -FLT_MAX) {
        // all-masked row: softmax over all-equal logits -> uniform over all 256 (incl. -1.0 pads)
        #pragma unroll
        for (int d = 0; d < DHD; d++) acc[d] = 0.f;
        for (int j = 0; j < 2*WSZ; j++) {
            const float* vr = vs + j * KPITCH;
            #pragma unroll
            for (int d = 0; d < DHD; d++) acc[d] += vr[d];
        }
        l = 256.f;
    }
    float inv = 1.f / l;
    size_t obase = (size_t)(b * NN + w * WSZ + i) * INNER + h * DHD;
    #pragma unroll
    for (int d = 0; d < DHD; d++) o[obase + d] = roundtf(acc[d] * inv);
}

// ---------------- GEGLU -> tf32-rounded, zero pad to FFP ----------------
__global__ __launch_bounds__(256) void geglu_kernel(
    const float* __restrict__ u, float* __restrict__ t)
{
    int mrow = blockIdx.x;
    const float* ur = u + (size_t)mrow * FF2P;
    float* tr = t + (size_t)mrow * FFP;
    for (int f = threadIdx.x; f < FFP; f += 256) {
        float r = 0.f;
        if (f < FFD) {
            float a = ur[f], g = ur[FFD + f];
            float ge = 0.5f * g * (1.f + erff(g * 0.70710678118654752f));
            r = roundtf(a * ge);
        }
        tr[f] = r;
    }
}

// ---------------- launch ----------------
extern "C" void kernel_launch(void* const* d_in, const int* in_sizes, int n_in,
                              void* d_out, int out_size)
{
    const int*   x        = (const int*)  d_in[0];
    const float* emb      = (const float*)d_in[1];
    const float* ln_ag    = (const float*)d_in[2];
    const float* ln_ab    = (const float*)d_in[3];
    const float* w_qkv    = (const float*)d_in[4];
    const float* w_out    = (const float*)d_in[5];
    const float* ln_fg    = (const float*)d_in[6];
    const float* ln_fb    = (const float*)d_in[7];
    const float* w_ff1    = (const float*)d_in[8];
    const float* w_ff2    = (const float*)d_in[9];
    const float* dpb_w1   = (const float*)d_in[10];
    const float* dpb_b1   = (const float*)d_in[11];
    const float* dpb_w2   = (const float*)d_in[12];
    const float* dpb_b2   = (const float*)d_in[13];
    const float* dpb_w3   = (const float*)d_in[14];
    const float* dpb_b3   = (const float*)d_in[15];
    const float* ln_og    = (const float*)d_in[16];
    const float* ln_ob    = (const float*)d_in[17];
    const float* w_logits = (const float*)d_in[18];
    float* out = (float*)d_out;

    float *h, *z, *qkv, *o, *u, *t, *pos, *tab;
    float *wqkvr, *woutr, *wff1p, *wff2p, *wlogr;
    cudaGetSymbolAddress((void**)&h,     g_h);
    cudaGetSymbolAddress((void**)&z,     g_z);
    cudaGetSymbolAddress((void**)&qkv,   g_qkv);
    cudaGetSymbolAddress((void**)&o,     g_o);
    cudaGetSymbolAddress((void**)&u,     g_u);
    cudaGetSymbolAddress((void**)&t,     g_t);
    cudaGetSymbolAddress((void**)&pos,   g_pos);
    cudaGetSymbolAddress((void**)&tab,   g_tab);
    cudaGetSymbolAddress((void**)&wqkvr, g_wqkvr);
    cudaGetSymbolAddress((void**)&woutr, g_woutr);
    cudaGetSymbolAddress((void**)&wff1p, g_wff1p);
    cudaGetSymbolAddress((void**)&wff2p, g_wff2p);
    cudaGetSymbolAddress((void**)&wlogr, g_wlogr);

    cudaFuncSetAttribute(attn_kernel, cudaFuncAttributeMaxDynamicSharedMemorySize, ATTN_SMEM);
    cudaFuncSetAttribute(tgemm_kernel, cudaFuncAttributeMaxDynamicSharedMemorySize, GEMM_SMEM);

    pos_kernel   <<<NN, 128>>>(pos);
    embed_kernel <<<TT, 128>>>(x, emb, pos, h);
    dpb_tab_kernel <<<2*WSZ, 256>>>(dpb_w1, dpb_b1, dpb_w2, dpb_b2, dpb_w3, dpb_b3, tab);

    // weight prep: tf32 rounding (+ padding for FF dims)
    {
        size_t n;
        n = (size_t)LL * DD * 3*INNER;
        padw_kernel<<<(unsigned)((n + 255)/256), 256>>>(w_qkv, wqkvr, 1, LL*DD, 3*INNER, LL*DD, 3*INNER);
        n = (size_t)LL * INNER * DD;
        padw_kernel<<<(unsigned)((n + 255)/256), 256>>>(w_out, woutr, 1, LL*INNER, DD, LL*INNER, DD);
        n = (size_t)LL * DD * FF2P;
        padw_kernel<<<(unsigned)((n + 255)/256), 256>>>(w_ff1, wff1p, LL, DD, FF2, DD, FF2P);
        n = (size_t)LL * FFP * DD;
        padw_kernel<<<(unsigned)((n + 255)/256), 256>>>(w_ff2, wff2p, LL, FFD, DD, FFP, DD);
        n = (size_t)DD * DD;
        padw_kernel<<<(unsigned)((n + 255)/256), 256>>>(w_logits, wlogr, 1, DD, DD, DD, DD);
    }

    for (int l = 0; l < LL; l++) {
        ln_kernel<<<TT, 128>>>(h, ln_ag + (size_t)l*DD, ln_ab + (size_t)l*DD, z);
        tgemm_kernel<<<dim3(12, 128), 256, GEMM_SMEM>>>(z, wqkvr + (size_t)l*DD*3*INNER, qkv,
                                                        TT, 3*INNER, DD, 0);
        attn_kernel<<<dim3(NWIN, HH, BB), 128, ATTN_SMEM>>>(qkv, x, tab, o);
        tgemm_kernel<<<dim3(4, 128), 256, GEMM_SMEM>>>(o, woutr + (size_t)l*INNER*DD, h,
                                                       TT, DD, INNER, 1);
        ln_kernel<<<TT, 128>>>(h, ln_fg + (size_t)l*DD, ln_fb + (size_t)l*DD, z);
        tgemm_kernel<<<dim3(FF2P/128, 128), 256, GEMM_SMEM>>>(z, wff1p + (size_t)l*DD*FF2P, u,
                                                              TT, FF2P, DD, 0);
        geglu_kernel<<<TT, 256>>>(u, t);
        tgemm_kernel<<<dim3(4, 128), 256, GEMM_SMEM>>>(t, wff2p + (size_t)l*FFP*DD, h,
                                                       TT, DD, FFP, 1);
    }
    ln_kernel<<<TT, 128>>>(h, ln_og, ln_ob, z);
    tgemm_kernel<<<dim3(4, 128), 256, GEMM_SMEM>>>(z, wlogr, out, TT, DD, DD, 0);
}